// round 10
// baseline (speedup 1.0000x reference)
#include <cuda_runtime.h>
#include <cuda.h>
#include <cuda_fp16.h>
#include <cstdint>

#define N_ENC     16384
#define N_LEVELS  16
#define HMASK     16383u
#define P2C       2654435761u
#define P3C       805459861u
#define TILES     18
#define NPAIRS    8
#define THREADS   1024
#define CHUNK     1024

__constant__ int c_res[N_LEVELS] = {16, 21, 26, 32, 41, 51, 64, 81,
                                    102, 128, 162, 204, 256, 323, 407, 512};

// g_tables[level][n] = half2(emb[0][n][level], emb[1][n][level])
__device__ __half2 g_tables[N_LEVELS][N_ENC];   // 1 MB static scratch (allowed)

__global__ void pack_tables_kernel(const float* __restrict__ emb) {
    int i = blockIdx.x * blockDim.x + threadIdx.x;
    if (i < N_LEVELS * N_ENC) {
        int l = i & (N_LEVELS - 1);
        int n = i >> 4;
        float e0 = emb[n * N_LEVELS + l];
        float e1 = emb[N_ENC * N_LEVELS + n * N_LEVELS + l];
        g_tables[l][n] = __floats2half2_rn(e0, e1);
    }
}

// ---------------------------------------------------------------------------
// Per-level trilinear hashed interpolation out of an SMEM fp16x2 table.
// ---------------------------------------------------------------------------
__device__ __forceinline__ float2 interp_level(const unsigned* __restrict__ tab,
                                               int res, float xi, float yi, float zi) {
    const float resf = (float)res;
    const float px = ((xi + 1.0f) * resf - 1.0f) * 0.5f;
    const float py = ((yi + 1.0f) * resf - 1.0f) * 0.5f;
    const float pz = ((zi + 1.0f) * resf - 1.0f) * 0.5f;

    const float fxf = floorf(px), fyf = floorf(py), fzf = floorf(pz);
    const float fx = px - fxf, fy = py - fyf, fz = pz - fzf;
    const int ix = (int)fxf, iy = (int)fyf, iz = (int)fzf;

    const float wx0 = (ix >= 0)       ? (1.0f - fx) : 0.0f;
    const float wx1 = (ix < res - 1)  ? fx          : 0.0f;
    const float wy0 = (iy >= 0)       ? (1.0f - fy) : 0.0f;
    const float wy1 = (iy < res - 1)  ? fy          : 0.0f;
    const float wz0 = (iz >= 0)       ? (1.0f - fz) : 0.0f;
    const float wz1 = (iz < res - 1)  ? fz          : 0.0f;

    const unsigned ax0 = (unsigned)ix * P3C;  const unsigned ax1 = ax0 + P3C;
    const unsigned ay0 = (unsigned)iy * P2C;  const unsigned ay1 = ay0 + P2C;
    const unsigned az0 = (unsigned)iz;        const unsigned az1 = az0 + 1u;

    const unsigned hyz00 = az0 ^ ay0;
    const unsigned hyz01 = az1 ^ ay0;
    const unsigned hyz10 = az0 ^ ay1;
    const unsigned hyz11 = az1 ^ ay1;

    const unsigned u0 = tab[(hyz00 ^ ax0) & HMASK];
    const unsigned u1 = tab[(hyz01 ^ ax0) & HMASK];
    const unsigned u2 = tab[(hyz10 ^ ax0) & HMASK];
    const unsigned u3 = tab[(hyz11 ^ ax0) & HMASK];
    const unsigned u4 = tab[(hyz00 ^ ax1) & HMASK];
    const unsigned u5 = tab[(hyz01 ^ ax1) & HMASK];
    const unsigned u6 = tab[(hyz10 ^ ax1) & HMASK];
    const unsigned u7 = tab[(hyz11 ^ ax1) & HMASK];

    const float wyz00 = wy0 * wz0;
    const float wyz01 = wy0 * wz1;
    const float wyz10 = wy1 * wz0;
    const float wyz11 = wy1 * wz1;

    const float w0 = wx0 * wyz00;
    const float w1 = wx0 * wyz01;
    const float w2 = wx0 * wyz10;
    const float w3 = wx0 * wyz11;
    const float w4 = wx1 * wyz00;
    const float w5 = wx1 * wyz01;
    const float w6 = wx1 * wyz10;
    const float w7 = wx1 * wyz11;

    float2 v;
    v = __half22float2(*(const __half2*)&u0);
    float accx = w0 * v.x, accy = w0 * v.y;
    v = __half22float2(*(const __half2*)&u1); accx += w1 * v.x; accy += w1 * v.y;
    v = __half22float2(*(const __half2*)&u2); accx += w2 * v.x; accy += w2 * v.y;
    v = __half22float2(*(const __half2*)&u3); accx += w3 * v.x; accy += w3 * v.y;
    v = __half22float2(*(const __half2*)&u4); accx += w4 * v.x; accy += w4 * v.y;
    v = __half22float2(*(const __half2*)&u5); accx += w5 * v.x; accy += w5 * v.y;
    v = __half22float2(*(const __half2*)&u6); accx += w6 * v.x; accy += w6 * v.y;
    v = __half22float2(*(const __half2*)&u7); accx += w7 * v.x; accy += w7 * v.y;

    return make_float2(accx, accy);
}

// ---------------------------------------------------------------------------
// TMA-store variant: compute into a SMEM staging buffer (STS.128, 4 wf) and
// let the TMA engine do the 16B-per-128B strided global writes (off the
// warp-issued l1tex wavefront path). Double-buffered, 4x (16B x 256-row)
// boxes per 1024-point chunk. Output tensor viewed as uint32[npoints][32].
// ---------------------------------------------------------------------------
__global__ void __launch_bounds__(THREADS, 1)
hash_enc_tma_kernel(const __grid_constant__ CUtensorMap tmap,
                    const float* __restrict__ x,
                    int npoints, int ppt) {
    extern __shared__ unsigned s_tab[];           // 2*16384 u32 = 128 KB tables
    float4* stage0 = reinterpret_cast<float4*>(s_tab + 2 * N_ENC);  // 16 KB
    float4* stage1 = stage0 + CHUNK;                                 // 16 KB

    const int pair = blockIdx.x & (NPAIRS - 1);
    const int tile = blockIdx.x / NPAIRS;
    const int lvl0 = pair * 2;

    {
        const float4* __restrict__ src = reinterpret_cast<const float4*>(g_tables[lvl0]);
        float4* dst = reinterpret_cast<float4*>(s_tab);
        for (int i = threadIdx.x; i < (2 * N_ENC) / 4; i += THREADS)
            dst[i] = src[i];
    }
    __syncthreads();

    const unsigned* tab0 = s_tab;
    const unsigned* tab1 = s_tab + N_ENC;
    const int res0 = c_res[lvl0];
    const int res1 = c_res[lvl0 + 1];

    const int p0  = tile * ppt;
    const int nch = ppt / CHUNK;

    for (int c = 0; c < nch; c++) {
        const int base = p0 + c * CHUNK;
        if (base >= npoints) break;            // uniform across CTA
        float4* stg = (c & 1) ? stage1 : stage0;

        // Buffer reuse gate: chunk c-2's TMA must have read this buffer.
        if (c >= 2 && threadIdx.x == 0)
            asm volatile("cp.async.bulk.wait_group.read 1;" ::: "memory");
        __syncthreads();

        const int p = base + (int)threadIdx.x;
        if (p < npoints) {
            const float xi = x[3 * p + 0];
            const float yi = x[3 * p + 1];
            const float zi = x[3 * p + 2];
            const float2 f0 = interp_level(tab0, res0, xi, yi, zi);
            const float2 f1 = interp_level(tab1, res1, xi, yi, zi);
            stg[threadIdx.x] = make_float4(f0.x, f0.y, f1.x, f1.y);
        }
        __syncthreads();

        if (threadIdx.x == 0) {
            asm volatile("fence.proxy.async.shared::cta;" ::: "memory");
            unsigned sa = (unsigned)__cvta_generic_to_shared(stg);
            const int cx = pair * 4;           // uint32 column offset
            #pragma unroll
            for (int q = 0; q < 4; q++) {
                asm volatile(
                    "cp.async.bulk.tensor.2d.global.shared::cta.tile.bulk_group "
                    "[%0, {%1, %2}], [%3];"
                    :: "l"(&tmap), "r"(cx), "r"(base + q * 256),
                       "r"(sa + (unsigned)(q * 256 * 16))
                    : "memory");
            }
            asm volatile("cp.async.bulk.commit_group;" ::: "memory");
        }
    }
    // Drain all pending bulk stores before exit.
    if (threadIdx.x == 0)
        asm volatile("cp.async.bulk.wait_group 0;" ::: "memory");
}

// ---------------------------------------------------------------------------
// Fallback (proven R9 path): direct strided STG.128.
// ---------------------------------------------------------------------------
__global__ void __launch_bounds__(THREADS, 1)
hash_enc_stg_kernel(const float* __restrict__ x, float4* __restrict__ out,
                    int npoints, int ppt) {
    extern __shared__ unsigned s_tab[];

    const int pair = blockIdx.x & (NPAIRS - 1);
    const int tile = blockIdx.x / NPAIRS;
    const int lvl0 = pair * 2;

    {
        const float4* __restrict__ src = reinterpret_cast<const float4*>(g_tables[lvl0]);
        float4* dst = reinterpret_cast<float4*>(s_tab);
        for (int i = threadIdx.x; i < (2 * N_ENC) / 4; i += THREADS)
            dst[i] = src[i];
    }
    __syncthreads();

    const unsigned* tab0 = s_tab;
    const unsigned* tab1 = s_tab + N_ENC;
    const int res0 = c_res[lvl0];
    const int res1 = c_res[lvl0 + 1];

    const int p0 = tile * ppt;
    const int p1 = (p0 + ppt < npoints) ? (p0 + ppt) : npoints;

    for (int p = p0 + (int)threadIdx.x; p < p1; p += THREADS) {
        const float xi = x[3 * p + 0];
        const float yi = x[3 * p + 1];
        const float zi = x[3 * p + 2];
        const float2 f0 = interp_level(tab0, res0, xi, yi, zi);
        const float2 f1 = interp_level(tab1, res1, xi, yi, zi);
        out[(size_t)p * NPAIRS + pair] = make_float4(f0.x, f0.y, f1.x, f1.y);
    }
}

// ---------------------------------------------------------------------------
typedef CUresult (*EncodeFn)(CUtensorMap*, CUtensorMapDataType, cuuint32_t, void*,
                             const cuuint64_t*, const cuuint64_t*,
                             const cuuint32_t*, const cuuint32_t*,
                             CUtensorMapInterleave, CUtensorMapSwizzle,
                             CUtensorMapL2promotion, CUtensorMapFloatOOBfill);

extern "C" void kernel_launch(void* const* d_in, const int* in_sizes, int n_in,
                              void* d_out, int out_size) {
    const float* x   = (const float*)d_in[0];
    const float* emb = (const float*)d_in[1];
    int nx = in_sizes[0];
    if (n_in >= 2 && in_sizes[0] == 2 * N_ENC * N_LEVELS && in_sizes[1] != 2 * N_ENC * N_LEVELS) {
        emb = (const float*)d_in[0];
        x   = (const float*)d_in[1];
        nx  = in_sizes[1];
    }
    const int npoints = nx / 3;

    // ppt: multiple of CHUNK so only the globally-last chunk is partial
    // (its excess rows exceed the tensor extent and TMA clips them).
    const int chunks_per_tile = (npoints + TILES * CHUNK - 1) / (TILES * CHUNK);
    const int ppt = chunks_per_tile * CHUNK;

    pack_tables_kernel<<<(N_LEVELS * N_ENC + 255) / 256, 256>>>(emb);

    // Resolve cuTensorMapEncodeTiled through the runtime (no -lcuda link dep).
    EncodeFn enc = nullptr;
    {
        void* fp = nullptr;
        cudaDriverEntryPointQueryResult qr = cudaDriverEntryPointSymbolNotFound;
#if CUDART_VERSION >= 12050
        if (cudaGetDriverEntryPointByVersion("cuTensorMapEncodeTiled", &fp, 12000,
                                             cudaEnableDefault, &qr) == cudaSuccess &&
            qr == cudaDriverEntryPointSuccess)
            enc = (EncodeFn)fp;
#else
        if (cudaGetDriverEntryPoint("cuTensorMapEncodeTiled", &fp,
                                    cudaEnableDefault, &qr) == cudaSuccess &&
            qr == cudaDriverEntryPointSuccess)
            enc = (EncodeFn)fp;
#endif
    }

    bool tma_ok = false;
    CUtensorMap tmap;
    if (enc) {
        // Output viewed as uint32 tensor [npoints][32], row stride 128 B.
        cuuint64_t dims[2]    = {32, (cuuint64_t)npoints};
        cuuint64_t strides[1] = {128};
        cuuint32_t box[2]     = {4, 256};
        cuuint32_t es[2]      = {1, 1};
        CUresult r = enc(&tmap, CU_TENSOR_MAP_DATA_TYPE_UINT32, 2, d_out,
                         dims, strides, box, es,
                         CU_TENSOR_MAP_INTERLEAVE_NONE, CU_TENSOR_MAP_SWIZZLE_NONE,
                         CU_TENSOR_MAP_L2_PROMOTION_L2_128B,
                         CU_TENSOR_MAP_FLOAT_OOB_FILL_NONE);
        tma_ok = (r == CUDA_SUCCESS);
    }

    if (tma_ok) {
        const int smem = 2 * N_ENC * (int)sizeof(unsigned) + 2 * CHUNK * 16;
        cudaFuncSetAttribute(hash_enc_tma_kernel,
                             cudaFuncAttributeMaxDynamicSharedMemorySize, smem);
        hash_enc_tma_kernel<<<TILES * NPAIRS, THREADS, smem>>>(tmap, x, npoints, ppt);
    } else {
        const int smem = 2 * N_ENC * (int)sizeof(unsigned);
        cudaFuncSetAttribute(hash_enc_stg_kernel,
                             cudaFuncAttributeMaxDynamicSharedMemorySize, smem);
        hash_enc_stg_kernel<<<TILES * NPAIRS, THREADS, smem>>>(
            x, (float4*)d_out, npoints, ppt);
    }
}

// round 12
// speedup vs baseline: 1.3025x; 1.3025x over previous
#include <cuda_runtime.h>
#include <cuda.h>
#include <cuda_fp16.h>
#include <cstdint>

#define N_ENC     16384
#define N_LEVELS  16
#define HMASK     16383u
#define P2C       2654435761u
#define P3C       805459861u
#define TILES     18
#define NPAIRS    8
#define THREADS   1024
#define NWARPS    (THREADS / 32)
#define NBUF      4

__constant__ int c_res[N_LEVELS] = {16, 21, 26, 32, 41, 51, 64, 81,
                                    102, 128, 162, 204, 256, 323, 407, 512};

// g_tables[level][n] = half2(emb[0][n][level], emb[1][n][level])
__device__ __half2 g_tables[N_LEVELS][N_ENC];   // 1 MB static scratch (allowed)

__global__ void pack_tables_kernel(const float* __restrict__ emb) {
    int i = blockIdx.x * blockDim.x + threadIdx.x;
    if (i < N_LEVELS * N_ENC) {
        int l = i & (N_LEVELS - 1);
        int n = i >> 4;
        float e0 = emb[n * N_LEVELS + l];
        float e1 = emb[N_ENC * N_LEVELS + n * N_LEVELS + l];
        g_tables[l][n] = __floats2half2_rn(e0, e1);
    }
}

// ---------------------------------------------------------------------------
// Per-level trilinear hashed interpolation out of an SMEM fp16x2 table.
// ---------------------------------------------------------------------------
__device__ __forceinline__ float2 interp_level(const unsigned* __restrict__ tab,
                                               int res, float xi, float yi, float zi) {
    const float resf = (float)res;
    const float px = ((xi + 1.0f) * resf - 1.0f) * 0.5f;
    const float py = ((yi + 1.0f) * resf - 1.0f) * 0.5f;
    const float pz = ((zi + 1.0f) * resf - 1.0f) * 0.5f;

    const float fxf = floorf(px), fyf = floorf(py), fzf = floorf(pz);
    const float fx = px - fxf, fy = py - fyf, fz = pz - fzf;
    const int ix = (int)fxf, iy = (int)fyf, iz = (int)fzf;

    const float wx0 = (ix >= 0)       ? (1.0f - fx) : 0.0f;
    const float wx1 = (ix < res - 1)  ? fx          : 0.0f;
    const float wy0 = (iy >= 0)       ? (1.0f - fy) : 0.0f;
    const float wy1 = (iy < res - 1)  ? fy          : 0.0f;
    const float wz0 = (iz >= 0)       ? (1.0f - fz) : 0.0f;
    const float wz1 = (iz < res - 1)  ? fz          : 0.0f;

    const unsigned ax0 = (unsigned)ix * P3C;  const unsigned ax1 = ax0 + P3C;
    const unsigned ay0 = (unsigned)iy * P2C;  const unsigned ay1 = ay0 + P2C;
    const unsigned az0 = (unsigned)iz;        const unsigned az1 = az0 + 1u;

    const unsigned hyz00 = az0 ^ ay0;
    const unsigned hyz01 = az1 ^ ay0;
    const unsigned hyz10 = az0 ^ ay1;
    const unsigned hyz11 = az1 ^ ay1;

    const unsigned u0 = tab[(hyz00 ^ ax0) & HMASK];
    const unsigned u1 = tab[(hyz01 ^ ax0) & HMASK];
    const unsigned u2 = tab[(hyz10 ^ ax0) & HMASK];
    const unsigned u3 = tab[(hyz11 ^ ax0) & HMASK];
    const unsigned u4 = tab[(hyz00 ^ ax1) & HMASK];
    const unsigned u5 = tab[(hyz01 ^ ax1) & HMASK];
    const unsigned u6 = tab[(hyz10 ^ ax1) & HMASK];
    const unsigned u7 = tab[(hyz11 ^ ax1) & HMASK];

    const float wyz00 = wy0 * wz0;
    const float wyz01 = wy0 * wz1;
    const float wyz10 = wy1 * wz0;
    const float wyz11 = wy1 * wz1;

    const float w0 = wx0 * wyz00;
    const float w1 = wx0 * wyz01;
    const float w2 = wx0 * wyz10;
    const float w3 = wx0 * wyz11;
    const float w4 = wx1 * wyz00;
    const float w5 = wx1 * wyz01;
    const float w6 = wx1 * wyz10;
    const float w7 = wx1 * wyz11;

    float2 v;
    v = __half22float2(*(const __half2*)&u0);
    float accx = w0 * v.x, accy = w0 * v.y;
    v = __half22float2(*(const __half2*)&u1); accx += w1 * v.x; accy += w1 * v.y;
    v = __half22float2(*(const __half2*)&u2); accx += w2 * v.x; accy += w2 * v.y;
    v = __half22float2(*(const __half2*)&u3); accx += w3 * v.x; accy += w3 * v.y;
    v = __half22float2(*(const __half2*)&u4); accx += w4 * v.x; accy += w4 * v.y;
    v = __half22float2(*(const __half2*)&u5); accx += w5 * v.x; accy += w5 * v.y;
    v = __half22float2(*(const __half2*)&u6); accx += w6 * v.x; accy += w6 * v.y;
    v = __half22float2(*(const __half2*)&u7); accx += w7 * v.x; accy += w7 * v.y;

    return make_float2(accx, accy);
}

// ---------------------------------------------------------------------------
// Per-warp TMA-store pipeline: NO CTA-wide barriers after the table stage.
// Each warp owns NBUF x 512 B staging slots; computes 32 contiguous points,
// syncwarp, lane 0 fences + issues one 2D TMA store (16 B x 32 rows) +
// commit_group. Slot reuse gated by wait_group.read NBUF-1 BEFORE the STS;
// the next iteration's 16 LDS gathers issue before any sync, preserving
// cross-warp latency hiding. Output tensor viewed as uint32[npoints][32].
// ---------------------------------------------------------------------------
__global__ void __launch_bounds__(THREADS, 1)
hash_enc_tma_kernel(const __grid_constant__ CUtensorMap tmap,
                    const float* __restrict__ x,
                    int npoints, int ppt) {
    extern __shared__ unsigned s_tab[];           // 2*16384 u32 = 128 KB tables
    float4* stages = reinterpret_cast<float4*>(s_tab + 2 * N_ENC);  // 64 KB

    const int pair = blockIdx.x & (NPAIRS - 1);
    const int tile = blockIdx.x / NPAIRS;
    const int lvl0 = pair * 2;

    {
        const float4* __restrict__ src = reinterpret_cast<const float4*>(g_tables[lvl0]);
        float4* dst = reinterpret_cast<float4*>(s_tab);
        for (int i = threadIdx.x; i < (2 * N_ENC) / 4; i += THREADS)
            dst[i] = src[i];
    }
    __syncthreads();

    const unsigned* tab0 = s_tab;
    const unsigned* tab1 = s_tab + N_ENC;
    const int res0 = c_res[lvl0];
    const int res1 = c_res[lvl0 + 1];

    const int warp = (int)threadIdx.x >> 5;
    const int lane = (int)threadIdx.x & 31;
    float4* my_stage = stages + warp * (NBUF * 32);   // 4 slots x 32 float4

    const int p0    = tile * ppt;
    const int p_end = (p0 + ppt < npoints) ? (p0 + ppt) : npoints;
    const int cx    = pair * 4;                        // uint32 column offset

    int it = 0;
    for (int pbase = p0 + warp * 32; pbase < p_end; pbase += THREADS, it++) {
        const int p = pbase + lane;

        // Compute first (long-latency LDS work, independent of staging slots).
        float xi = 0.f, yi = 0.f, zi = 0.f;
        if (p < npoints) {
            xi = x[3 * p + 0];
            yi = x[3 * p + 1];
            zi = x[3 * p + 2];
        }
        const float2 f0 = interp_level(tab0, res0, xi, yi, zi);
        const float2 f1 = interp_level(tab1, res1, xi, yi, zi);

        float4* slot = my_stage + (it & (NBUF - 1)) * 32;

        // Gate slot reuse: allow NBUF-1 groups in flight.
        if (it >= NBUF) {
            if (lane == 0)
                asm volatile("cp.async.bulk.wait_group.read %0;" :: "n"(NBUF - 1) : "memory");
            __syncwarp();
        }

        slot[lane] = make_float4(f0.x, f0.y, f1.x, f1.y);
        __syncwarp();

        if (lane == 0) {
            asm volatile("fence.proxy.async.shared::cta;" ::: "memory");
            unsigned sa = (unsigned)__cvta_generic_to_shared(slot);
            asm volatile(
                "cp.async.bulk.tensor.2d.global.shared::cta.tile.bulk_group "
                "[%0, {%1, %2}], [%3];"
                :: "l"(&tmap), "r"(cx), "r"(pbase), "r"(sa)
                : "memory");
            asm volatile("cp.async.bulk.commit_group;" ::: "memory");
        }
    }

    // Drain all pending bulk stores before SMEM goes away.
    if (lane == 0)
        asm volatile("cp.async.bulk.wait_group 0;" ::: "memory");
}

// ---------------------------------------------------------------------------
// Fallback (proven R9 path): direct strided STG.128.
// ---------------------------------------------------------------------------
__global__ void __launch_bounds__(THREADS, 1)
hash_enc_stg_kernel(const float* __restrict__ x, float4* __restrict__ out,
                    int npoints, int ppt) {
    extern __shared__ unsigned s_tab[];

    const int pair = blockIdx.x & (NPAIRS - 1);
    const int tile = blockIdx.x / NPAIRS;
    const int lvl0 = pair * 2;

    {
        const float4* __restrict__ src = reinterpret_cast<const float4*>(g_tables[lvl0]);
        float4* dst = reinterpret_cast<float4*>(s_tab);
        for (int i = threadIdx.x; i < (2 * N_ENC) / 4; i += THREADS)
            dst[i] = src[i];
    }
    __syncthreads();

    const unsigned* tab0 = s_tab;
    const unsigned* tab1 = s_tab + N_ENC;
    const int res0 = c_res[lvl0];
    const int res1 = c_res[lvl0 + 1];

    const int p0 = tile * ppt;
    const int p1 = (p0 + ppt < npoints) ? (p0 + ppt) : npoints;

    for (int p = p0 + (int)threadIdx.x; p < p1; p += THREADS) {
        const float xi = x[3 * p + 0];
        const float yi = x[3 * p + 1];
        const float zi = x[3 * p + 2];
        const float2 f0 = interp_level(tab0, res0, xi, yi, zi);
        const float2 f1 = interp_level(tab1, res1, xi, yi, zi);
        out[(size_t)p * NPAIRS + pair] = make_float4(f0.x, f0.y, f1.x, f1.y);
    }
}

// ---------------------------------------------------------------------------
typedef CUresult (*EncodeFn)(CUtensorMap*, CUtensorMapDataType, cuuint32_t, void*,
                             const cuuint64_t*, const cuuint64_t*,
                             const cuuint32_t*, const cuuint32_t*,
                             CUtensorMapInterleave, CUtensorMapSwizzle,
                             CUtensorMapL2promotion, CUtensorMapFloatOOBfill);

extern "C" void kernel_launch(void* const* d_in, const int* in_sizes, int n_in,
                              void* d_out, int out_size) {
    const float* x   = (const float*)d_in[0];
    const float* emb = (const float*)d_in[1];
    int nx = in_sizes[0];
    if (n_in >= 2 && in_sizes[0] == 2 * N_ENC * N_LEVELS && in_sizes[1] != 2 * N_ENC * N_LEVELS) {
        emb = (const float*)d_in[0];
        x   = (const float*)d_in[1];
        nx  = in_sizes[1];
    }
    const int npoints = nx / 3;
    const int ppt = (npoints + TILES - 1) / TILES;

    pack_tables_kernel<<<(N_LEVELS * N_ENC + 255) / 256, 256>>>(emb);

    // Resolve cuTensorMapEncodeTiled through the runtime (no -lcuda link dep).
    EncodeFn enc = nullptr;
    {
        void* fp = nullptr;
        cudaDriverEntryPointQueryResult qr = cudaDriverEntryPointSymbolNotFound;
#if CUDART_VERSION >= 12050
        if (cudaGetDriverEntryPointByVersion("cuTensorMapEncodeTiled", &fp, 12000,
                                             cudaEnableDefault, &qr) == cudaSuccess &&
            qr == cudaDriverEntryPointSuccess)
            enc = (EncodeFn)fp;
#else
        if (cudaGetDriverEntryPoint("cuTensorMapEncodeTiled", &fp,
                                    cudaEnableDefault, &qr) == cudaSuccess &&
            qr == cudaDriverEntryPointSuccess)
            enc = (EncodeFn)fp;
#endif
    }

    bool tma_ok = false;
    CUtensorMap tmap;
    if (enc) {
        // Output viewed as uint32 tensor [npoints][32], row stride 128 B.
        cuuint64_t dims[2]    = {32, (cuuint64_t)npoints};
        cuuint64_t strides[1] = {128};
        cuuint32_t box[2]     = {4, 32};
        cuuint32_t es[2]      = {1, 1};
        CUresult r = enc(&tmap, CU_TENSOR_MAP_DATA_TYPE_UINT32, 2, d_out,
                         dims, strides, box, es,
                         CU_TENSOR_MAP_INTERLEAVE_NONE, CU_TENSOR_MAP_SWIZZLE_NONE,
                         CU_TENSOR_MAP_L2_PROMOTION_L2_128B,
                         CU_TENSOR_MAP_FLOAT_OOB_FILL_NONE);
        tma_ok = (r == CUDA_SUCCESS);
    }

    if (tma_ok) {
        const int smem = 2 * N_ENC * (int)sizeof(unsigned) + NWARPS * NBUF * 32 * 16;
        cudaFuncSetAttribute(hash_enc_tma_kernel,
                             cudaFuncAttributeMaxDynamicSharedMemorySize, smem);
        hash_enc_tma_kernel<<<TILES * NPAIRS, THREADS, smem>>>(tmap, x, npoints, ppt);
    } else {
        const int smem = 2 * N_ENC * (int)sizeof(unsigned);
        cudaFuncSetAttribute(hash_enc_stg_kernel,
                             cudaFuncAttributeMaxDynamicSharedMemorySize, smem);
        hash_enc_stg_kernel<<<TILES * NPAIRS, THREADS, smem>>>(
            x, (float4*)d_out, npoints, ppt);
    }
}